// round 6
// baseline (speedup 1.0000x reference)
#include <cuda_runtime.h>

#define BATCH 8
#define NPIX  1024

__device__ float g_q   [BATCH*128*NPIX];     // [b][c][n]
__device__ float g_k   [BATCH*128*NPIX];     // [b][c][m]
__device__ float g_vT  [BATCH*NPIX*128];     // [b][m][c]
__device__ float g_gvT [BATCH*NPIX*128];     // [b][n][c]  (transposed gv)
__device__ float g_part[BATCH*64*128];
__device__ float g_ca  [BATCH*128];

// ---------------- K1: subsample + QKV projection ----------------
__global__ void __launch_bounds__(256) k_qkv(const float* __restrict__ x,
                                             const float* __restrict__ Wq,
                                             const float* __restrict__ Wk,
                                             const float* __restrict__ Wv) {
    __shared__ float xs[256*33];
    __shared__ float wt[16*132];
    int b = blockIdx.x, hs = blockIdx.y, tid = threadIdx.x;

    for (int idx = tid; idx < 256*32; idx += 256) {
        int c = idx >> 5, p = idx & 31;
        xs[c*33 + p] = x[(((b<<8) + c)*128 + (hs<<2))*128 + (p<<2)];
    }
    int to = tid >> 4, tp = tid & 15;
    int o0 = to*8, p0 = tp*2;
    int n  = (hs<<5) + p0;

    for (int mat = 0; mat < 3; mat++) {
        const float* W = (mat == 0) ? Wq : ((mat == 1) ? Wk : Wv);
        float acc[8][2];
        #pragma unroll
        for (int i = 0; i < 8; i++) { acc[i][0] = 0.f; acc[i][1] = 0.f; }

        for (int kc = 0; kc < 16; kc++) {
            __syncthreads();
            #pragma unroll
            for (int l = 0; l < 8; l++) {
                int idx = tid + l*256;
                int k = idx & 15, o = idx >> 4;
                wt[k*132 + o] = W[(o<<8) + (kc<<4) + k];
            }
            __syncthreads();
            #pragma unroll
            for (int k = 0; k < 16; k++) {
                float wv[8];
                *(float4*)&wv[0] = *(const float4*)&wt[k*132 + o0];
                *(float4*)&wv[4] = *(const float4*)&wt[k*132 + o0 + 4];
                float x0 = xs[((kc<<4)+k)*33 + p0];
                float x1 = xs[((kc<<4)+k)*33 + p0 + 1];
                #pragma unroll
                for (int i = 0; i < 8; i++) {
                    acc[i][0] += wv[i]*x0;
                    acc[i][1] += wv[i]*x1;
                }
            }
        }
        if (mat == 2) {
            #pragma unroll
            for (int j = 0; j < 2; j++)
                #pragma unroll
                for (int i = 0; i < 8; i++)
                    g_vT[(((b<<10) + n + j)<<7) + o0 + i] = acc[i][j];
        } else {
            float* dst = ((mat == 0) ? g_q : g_k) + (((b<<7) + o0)<<10) + n;
            #pragma unroll
            for (int i = 0; i < 8; i++) {
                dst[(i<<10) + 0] = acc[i][0];
                dst[(i<<10) + 1] = acc[i][1];
            }
        }
    }
}

// ---------------- K2: scores + softmax + gate + gv (fused, 16 rows/CTA) ----------------
#define S_PITCH  1028
#define KA_PITCH 68    // phase A: kv[c 128][m 64]
#define KC_PITCH 132   // phase C: kv[m 64][c 128]
#define Q_PITCH  20
// floats: scores 16*1028=16448, kv max(128*68=8704, 64*132=8448)=8704, qs 128*20=2560
#define SM2_F   (16448 + 8704 + 2560)
#define SMEM2_BYTES (SM2_F*4)

__global__ void __launch_bounds__(256,2) k_attn(float* __restrict__ gate_out) {
    extern __shared__ float sm[];
    float* s  = sm;                 // 16 x S_PITCH
    float* kv = sm + 16448;
    float* qs = kv + 8704;

    int b = blockIdx.x, nb = blockIdx.y;
    int n0 = nb << 4;
    int tid = threadIdx.x;
    int w = tid >> 5, lane = tid & 31;
    int rg = w >> 1;                // row group 0..3 (rows rg*4..rg*4+3)
    int mh = (w & 1) << 5;          // m half offset within 64-tile

    const float* qg  = g_q  + (size_t)b * (128*NPIX);
    const float* kg  = g_k  + (size_t)b * (128*NPIX);
    const float* vtg = g_vT + (size_t)b * (NPIX*128);

    for (int idx = tid; idx < 2048; idx += 256) {
        int c = idx >> 4, ni = idx & 15;
        qs[c*Q_PITCH + ni] = qg[(c<<10) + n0 + ni];
    }

    // -------- phase A: scores = Q^T K (16 tiles of 64 m) --------
    for (int mt = 0; mt < 16; mt++) {
        int m0 = mt << 6;
        __syncthreads();
        for (int i = tid; i < 2048; i += 256) {
            int c = i >> 4, ml = (i & 15) << 2;
            *(float4*)&kv[c*KA_PITCH + ml] = *(const float4*)&kg[(c<<10) + m0 + ml];
        }
        __syncthreads();
        float acc[4] = {0.f, 0.f, 0.f, 0.f};
        int ml = mh + lane;
        #pragma unroll 4
        for (int c = 0; c < 128; c++) {
            float4 qv = *(const float4*)&qs[c*Q_PITCH + (rg<<2)];   // broadcast
            float kk = kv[c*KA_PITCH + ml];
            acc[0] += qv.x*kk; acc[1] += qv.y*kk; acc[2] += qv.z*kk; acc[3] += qv.w*kk;
        }
        #pragma unroll
        for (int i = 0; i < 4; i++)
            s[((rg<<2)+i)*S_PITCH + m0 + ml] = acc[i];
    }
    __syncthreads();

    // -------- phase B: softmax, warp owns rows 2w, 2w+1 --------
    #pragma unroll
    for (int rr = 0; rr < 2; rr++) {
        int r = (w<<1) + rr;
        float* row = s + r*S_PITCH;
        float mx = -1e30f;
        for (int m = lane; m < 1024; m += 32) mx = fmaxf(mx, row[m]);
        #pragma unroll
        for (int off = 16; off; off >>= 1) mx = fmaxf(mx, __shfl_xor_sync(0xffffffffu, mx, off));
        float ssum = 0.f;
        for (int m = lane; m < 1024; m += 32) {
            float e = __expf(row[m] - mx);
            row[m] = e;
            ssum += e;
        }
        #pragma unroll
        for (int off = 16; off; off >>= 1) ssum += __shfl_xor_sync(0xffffffffu, ssum, off);
        float inv = 1.0f / ssum;
        float* go = gate_out + (((size_t)(b<<10) + n0 + r) << 10);
        for (int m = lane; m < 1024; m += 32) {
            float gte = row[m] * inv;
            row[m] = gte;
            go[m] = gte;
        }
    }
    __syncthreads();

    // -------- phase C: gv = gate @ V^T --------
    // warp w: rows rg*4..+3, m-half mh of each tile, c = lane*4..+3
    float4 a2[4];
    #pragma unroll
    for (int i = 0; i < 4; i++) a2[i] = make_float4(0.f,0.f,0.f,0.f);

    for (int mt = 0; mt < 16; mt++) {
        int m0 = mt << 6;
        __syncthreads();
        for (int i = tid; i < 2048; i += 256) {
            int m = i >> 5, c4 = (i & 31) << 2;
            *(float4*)&kv[m*KC_PITCH + c4] = *(const float4*)&vtg[((m0 + m) << 7) + c4];
        }
        __syncthreads();
        #pragma unroll 2
        for (int mm = 0; mm < 32; mm += 2) {
            int m = mh + mm;
            float2 g0 = *(const float2*)&s[((rg<<2)+0)*S_PITCH + m0 + m];
            float2 g1 = *(const float2*)&s[((rg<<2)+1)*S_PITCH + m0 + m];
            float2 g2 = *(const float2*)&s[((rg<<2)+2)*S_PITCH + m0 + m];
            float2 g3 = *(const float2*)&s[((rg<<2)+3)*S_PITCH + m0 + m];
            float4 va = *(const float4*)&kv[m*KC_PITCH + (lane<<2)];
            float4 vb = *(const float4*)&kv[(m+1)*KC_PITCH + (lane<<2)];
            a2[0].x += g0.x*va.x + g0.y*vb.x;  a2[0].y += g0.x*va.y + g0.y*vb.y;
            a2[0].z += g0.x*va.z + g0.y*vb.z;  a2[0].w += g0.x*va.w + g0.y*vb.w;
            a2[1].x += g1.x*va.x + g1.y*vb.x;  a2[1].y += g1.x*va.y + g1.y*vb.y;
            a2[1].z += g1.x*va.z + g1.y*vb.z;  a2[1].w += g1.x*va.w + g1.y*vb.w;
            a2[2].x += g2.x*va.x + g2.y*vb.x;  a2[2].y += g2.x*va.y + g2.y*vb.y;
            a2[2].z += g2.x*va.z + g2.y*vb.z;  a2[2].w += g2.x*va.w + g2.y*vb.w;
            a2[3].x += g3.x*va.x + g3.y*vb.x;  a2[3].y += g3.x*va.y + g3.y*vb.y;
            a2[3].z += g3.x*va.z + g3.y*vb.z;  a2[3].w += g3.x*va.w + g3.y*vb.w;
        }
    }

    // combine m-half partials: odd warp -> smem, even warp adds
    __syncthreads();
    if (w & 1) {
        #pragma unroll
        for (int i = 0; i < 4; i++)
            *(float4*)&kv[((rg<<2)+i)*128 + (lane<<2)] = a2[i];
    }
    __syncthreads();
    if (!(w & 1)) {
        #pragma unroll
        for (int i = 0; i < 4; i++) {
            float4 o = *(const float4*)&kv[((rg<<2)+i)*128 + (lane<<2)];
            a2[i].x += o.x; a2[i].y += o.y; a2[i].z += o.z; a2[i].w += o.w;
            *(float4*)&g_gvT[(((size_t)(b<<10) + n0 + (rg<<2) + i)<<7) + (lane<<2)] = a2[i];
        }
        float4 ps;
        ps.x = a2[0].x + a2[1].x + a2[2].x + a2[3].x;
        ps.y = a2[0].y + a2[1].y + a2[2].y + a2[3].y;
        ps.z = a2[0].z + a2[1].z + a2[2].z + a2[3].z;
        ps.w = a2[0].w + a2[1].w + a2[2].w + a2[3].w;
        *(float4*)&qs[rg*128 + (lane<<2)] = ps;
    }
    __syncthreads();
    if (tid < 128) {
        float p = qs[tid] + qs[128 + tid] + qs[256 + tid] + qs[384 + tid];
        g_part[(((b<<6) + nb)<<7) + tid] = p;
    }
}

// ---------------- K3: channel attention ----------------
__global__ void __launch_bounds__(128) k_ca(const float* __restrict__ w1d,
                                            float* __restrict__ ca_out) {
    __shared__ float cam[130];
    int b = blockIdx.x, c = threadIdx.x;
    float sum = 0.f;
    for (int nb = 0; nb < 64; nb++) sum += g_part[(((b<<6) + nb)<<7) + c];
    cam[c+1] = sum * (1.0f/1024.0f);
    if (c == 0) { cam[0] = 0.f; cam[129] = 0.f; }
    __syncthreads();
    float y = w1d[0]*cam[c] + w1d[1]*cam[c+1] + w1d[2]*cam[c+2];
    float sg = 1.0f / (1.0f + __expf(-y));
    g_ca[(b<<7) + c] = sg;
    ca_out[(b<<7) + c] = sg;
}

// ---------------- K4: conv3x3(gv * ca), 16 out-ch per CTA ----------------
__global__ void __launch_bounds__(256,4) k_conv(const float* __restrict__ Wc,
                                                float* __restrict__ out) {
    __shared__ float in_s[16*350];   // [c16][ry(10) pitch35][cx(34)]
    __shared__ float w_s [16*144];   // [o16][c16*9]
    __shared__ float ca_s[128];
    int b = blockIdx.x, ot = blockIdx.y, rt = blockIdx.z;
    int tid = threadIdx.x;
    int w = tid >> 5, lane = tid & 31;
    int row  = lane >> 2;            // 0..7
    int colb = (lane & 3) << 3;      // 0,8,16,24
    int r0 = rt << 3;

    if (tid < 128) ca_s[tid] = g_ca[(b<<7) + tid];

    float acc[2][8];
    #pragma unroll
    for (int i = 0; i < 2; i++)
        #pragma unroll
        for (int j = 0; j < 8; j++) acc[i][j] = 0.f;

    for (int cc = 0; cc < 8; cc++) {
        int cbase = cc << 4;
        __syncthreads();
        // input tile: 340 pixels x 16 ch, read gvT [b][pix][c] as float4 over c
        for (int idx = tid; idx < 1360; idx += 256) {
            int p  = idx >> 2;          // pixel 0..339
            int q4 = idx & 3;           // c-quad
            int ry = p / 34;
            int cx = p - ry*34;
            int gr = r0 - 1 + ry;
            int gc = cx - 1;
            float4 v = make_float4(0.f,0.f,0.f,0.f);
            if ((unsigned)gr < 32u && (unsigned)gc < 32u) {
                v = *(const float4*)&g_gvT[(((size_t)(b<<10) + (gr<<5) + gc)<<7) + cbase + (q4<<2)];
                const float* cap = &ca_s[cbase + (q4<<2)];
                v.x *= cap[0]; v.y *= cap[1]; v.z *= cap[2]; v.w *= cap[3];
            }
            float* d = &in_s[((q4<<2))*350 + ry*35 + cx];
            d[0] = v.x; d[350] = v.y; d[700] = v.z; d[1050] = v.w;
        }
        for (int idx = tid; idx < 2304; idx += 256) {
            int o   = idx / 144;
            int rem = idx - o*144;
            w_s[o*144 + rem] = Wc[(((ot<<4) + o)*128 + cbase)*9 + rem];
        }
        __syncthreads();

        for (int c = 0; c < 16; c++) {
            #pragma unroll
            for (int ky = 0; ky < 3; ky++) {
                const float* ir = &in_s[c*350 + (row + ky)*35 + colb];
                float iv[10];
                #pragma unroll
                for (int t = 0; t < 10; t++) iv[t] = ir[t];
                #pragma unroll
                for (int oo = 0; oo < 2; oo++) {
                    const float* wr = &w_s[((w<<1)+oo)*144 + c*9 + ky*3];
                    float w0 = wr[0], w1 = wr[1], w2 = wr[2];
                    #pragma unroll
                    for (int xx = 0; xx < 8; xx++)
                        acc[oo][xx] += w0*iv[xx] + w1*iv[xx+1] + w2*iv[xx+2];
                }
            }
        }
    }

    #pragma unroll
    for (int oo = 0; oo < 2; oo++) {
        float* dst = out + (((size_t)((b<<8) + (ot<<4) + (w<<1) + oo)*32 + r0 + row)<<5) + colb;
        *(float4*)&dst[0] = *(float4*)&acc[oo][0];
        *(float4*)&dst[4] = *(float4*)&acc[oo][4];
    }
}

extern "C" void kernel_launch(void* const* d_in, const int* in_sizes, int n_in,
                              void* d_out, int out_size) {
    const float* x   = (const float*)d_in[0];
    const float* Wq  = (const float*)d_in[1];
    const float* Wk  = (const float*)d_in[2];
    const float* Wv  = (const float*)d_in[3];
    const float* w1d = (const float*)d_in[4];
    const float* Wc  = (const float*)d_in[5];
    float* out_p  = (float*)d_out;
    float* gate_p = out_p + (size_t)BATCH*256*32*32;
    float* ca_p   = gate_p + (size_t)BATCH*NPIX*NPIX;

    cudaFuncSetAttribute(k_attn, cudaFuncAttributeMaxDynamicSharedMemorySize, SMEM2_BYTES);

    k_qkv <<<dim3(8,32), 256>>>(x, Wq, Wk, Wv);
    k_attn<<<dim3(8,64), 256, SMEM2_BYTES>>>(gate_p);
    k_ca  <<<8, 128>>>(w1d, ca_p);
    k_conv<<<dim3(8,16,4), 256>>>(Wc, out_p);
}

// round 8
// speedup vs baseline: 1.8185x; 1.8185x over previous
#include <cuda_runtime.h>

#define BATCH 8
#define NPIX  1024

__device__ float g_q  [BATCH*128*NPIX];
__device__ float g_k  [BATCH*128*NPIX];
__device__ float g_vT [BATCH*NPIX*128];
__device__ float g_gv [BATCH*128*NPIX];
__device__ float g_part[BATCH*32*128];
__device__ float g_ca [BATCH*128];

// ---------------- K1: subsample + QKV projection ----------------
__global__ void __launch_bounds__(256) k_qkv(const float* __restrict__ x,
                                             const float* __restrict__ Wq,
                                             const float* __restrict__ Wk,
                                             const float* __restrict__ Wv) {
    __shared__ float xs[256*33];
    __shared__ float wt[16*132];
    int b = blockIdx.x, hs = blockIdx.y, tid = threadIdx.x;

    for (int idx = tid; idx < 256*32; idx += 256) {
        int c = idx >> 5, p = idx & 31;
        xs[c*33 + p] = x[(((b<<8) + c)*128 + (hs<<2))*128 + (p<<2)];
    }
    int to = tid >> 4, tp = tid & 15;
    int o0 = to*8, p0 = tp*2;
    int n  = (hs<<5) + p0;

    for (int mat = 0; mat < 3; mat++) {
        const float* W = (mat == 0) ? Wq : ((mat == 1) ? Wk : Wv);
        float acc[8][2];
        #pragma unroll
        for (int i = 0; i < 8; i++) { acc[i][0] = 0.f; acc[i][1] = 0.f; }

        for (int kc = 0; kc < 16; kc++) {
            __syncthreads();
            #pragma unroll
            for (int l = 0; l < 8; l++) {
                int idx = tid + l*256;
                int k = idx & 15, o = idx >> 4;
                wt[k*132 + o] = W[(o<<8) + (kc<<4) + k];
            }
            __syncthreads();
            #pragma unroll
            for (int k = 0; k < 16; k++) {
                float wv[8];
                *(float4*)&wv[0] = *(const float4*)&wt[k*132 + o0];
                *(float4*)&wv[4] = *(const float4*)&wt[k*132 + o0 + 4];
                float x0 = xs[((kc<<4)+k)*33 + p0];
                float x1 = xs[((kc<<4)+k)*33 + p0 + 1];
                #pragma unroll
                for (int i = 0; i < 8; i++) {
                    acc[i][0] += wv[i]*x0;
                    acc[i][1] += wv[i]*x1;
                }
            }
        }
        if (mat == 2) {
            #pragma unroll
            for (int j = 0; j < 2; j++)
                #pragma unroll
                for (int i = 0; i < 8; i++)
                    g_vT[(((b<<10) + n + j)<<7) + o0 + i] = acc[i][j];
        } else {
            float* dst = ((mat == 0) ? g_q : g_k) + (((b<<7) + o0)<<10) + n;
            #pragma unroll
            for (int i = 0; i < 8; i++) {
                dst[(i<<10) + 0] = acc[i][0];
                dst[(i<<10) + 1] = acc[i][1];
            }
        }
    }
}

// ---------------- K2: scores + softmax + gate + gv (fused, 32 rows/CTA) ----------------
#define S_PITCH  1028
#define KV_PITCH 132
#define Q_PITCH  36
#define SMEM2_BYTES ((32*S_PITCH + 128*KV_PITCH + 128*Q_PITCH)*4)   // 217600

__global__ void __launch_bounds__(256) k_attn(float* __restrict__ gate_out) {
    extern __shared__ float sm[];
    float* s  = sm;
    float* kv = sm + 32*S_PITCH;
    float* qs = kv + 128*KV_PITCH;

    int b = blockIdx.x, nb = blockIdx.y;
    int n0 = nb << 5;
    int tid = threadIdx.x;
    int w = tid >> 5, lane = tid & 31;

    const float* qg  = g_q  + (size_t)b * (128*NPIX);
    const float* kg  = g_k  + (size_t)b * (128*NPIX);
    const float* vtg = g_vT + (size_t)b * (NPIX*128);

    for (int idx = tid; idx < 128*32; idx += 256) {
        int c = idx >> 5, ni = idx & 31;
        qs[c*Q_PITCH + ni] = qg[(c<<10) + n0 + ni];
    }

    // phase A: scores = Q^T K
    for (int mt = 0; mt < 8; mt++) {
        int m0 = mt << 7;
        __syncthreads();
        for (int i = tid; i < 4096; i += 256) {
            int c = i >> 5, m4 = (i & 31) << 2;
            *(float4*)&kv[c*KV_PITCH + m4] = *(const float4*)&kg[(c<<10) + m0 + m4];
        }
        __syncthreads();
        float acc[4][4];
        #pragma unroll
        for (int i = 0; i < 4; i++)
            #pragma unroll
            for (int j = 0; j < 4; j++) acc[i][j] = 0.f;

        #pragma unroll 4
        for (int c = 0; c < 128; c++) {
            float4 qv = *(const float4*)&qs[c*Q_PITCH + (w<<2)];
            float4 kk = *(const float4*)&kv[c*KV_PITCH + (lane<<2)];
            acc[0][0] += qv.x*kk.x; acc[0][1] += qv.x*kk.y; acc[0][2] += qv.x*kk.z; acc[0][3] += qv.x*kk.w;
            acc[1][0] += qv.y*kk.x; acc[1][1] += qv.y*kk.y; acc[1][2] += qv.y*kk.z; acc[1][3] += qv.y*kk.w;
            acc[2][0] += qv.z*kk.x; acc[2][1] += qv.z*kk.y; acc[2][2] += qv.z*kk.z; acc[2][3] += qv.z*kk.w;
            acc[3][0] += qv.w*kk.x; acc[3][1] += qv.w*kk.y; acc[3][2] += qv.w*kk.z; acc[3][3] += qv.w*kk.w;
        }
        #pragma unroll
        for (int i = 0; i < 4; i++) {
            float4 v4; v4.x = acc[i][0]; v4.y = acc[i][1]; v4.z = acc[i][2]; v4.w = acc[i][3];
            *(float4*)&s[((w<<2) + i)*S_PITCH + m0 + (lane<<2)] = v4;
        }
    }
    __syncwarp();

    // phase B: softmax over warp-private rows, write gate
    #pragma unroll
    for (int rr = 0; rr < 4; rr++) {
        int r = (w<<2) + rr;
        float* row = s + r*S_PITCH;
        float mx = -1e30f;
        for (int m = lane; m < 1024; m += 32) mx = fmaxf(mx, row[m]);
        #pragma unroll
        for (int off = 16; off; off >>= 1) mx = fmaxf(mx, __shfl_xor_sync(0xffffffffu, mx, off));
        float ssum = 0.f;
        for (int m = lane; m < 1024; m += 32) {
            float e = __expf(row[m] - mx);
            row[m] = e;
            ssum += e;
        }
        #pragma unroll
        for (int off = 16; off; off >>= 1) ssum += __shfl_xor_sync(0xffffffffu, ssum, off);
        float inv = 1.0f / ssum;
        float* go = gate_out + (((size_t)(b<<10) + n0 + r) << 10);
        for (int m = lane; m < 1024; m += 32) {
            float gte = row[m] * inv;
            row[m] = gte;
            go[m] = gte;
        }
    }

    // phase C: gv = gate @ V^T
    float a2[4][4];
    #pragma unroll
    for (int i = 0; i < 4; i++)
        #pragma unroll
        for (int j = 0; j < 4; j++) a2[i][j] = 0.f;

    for (int mt = 0; mt < 8; mt++) {
        int m0 = mt << 7;
        __syncthreads();
        for (int i = tid; i < 4096; i += 256) {
            int m = i >> 5, c4 = (i & 31) << 2;
            *(float4*)&kv[m*KV_PITCH + c4] = *(const float4*)&vtg[((m0 + m) << 7) + c4];
        }
        __syncthreads();
        for (int m = 0; m < 128; m += 2) {
            float2 g0 = *(const float2*)&s[((w<<2)+0)*S_PITCH + m0 + m];
            float2 g1 = *(const float2*)&s[((w<<2)+1)*S_PITCH + m0 + m];
            float2 g2 = *(const float2*)&s[((w<<2)+2)*S_PITCH + m0 + m];
            float2 g3 = *(const float2*)&s[((w<<2)+3)*S_PITCH + m0 + m];
            float4 va = *(const float4*)&kv[m*KV_PITCH + (lane<<2)];
            float4 vb = *(const float4*)&kv[(m+1)*KV_PITCH + (lane<<2)];
            a2[0][0] += g0.x*va.x + g0.y*vb.x;  a2[0][1] += g0.x*va.y + g0.y*vb.y;
            a2[0][2] += g0.x*va.z + g0.y*vb.z;  a2[0][3] += g0.x*va.w + g0.y*vb.w;
            a2[1][0] += g1.x*va.x + g1.y*vb.x;  a2[1][1] += g1.x*va.y + g1.y*vb.y;
            a2[1][2] += g1.x*va.z + g1.y*vb.z;  a2[1][3] += g1.x*va.w + g1.y*vb.w;
            a2[2][0] += g2.x*va.x + g2.y*vb.x;  a2[2][1] += g2.x*va.y + g2.y*vb.y;
            a2[2][2] += g2.x*va.z + g2.y*vb.z;  a2[2][3] += g2.x*va.w + g2.y*vb.w;
            a2[3][0] += g3.x*va.x + g3.y*vb.x;  a2[3][1] += g3.x*va.y + g3.y*vb.y;
            a2[3][2] += g3.x*va.z + g3.y*vb.z;  a2[3][3] += g3.x*va.w + g3.y*vb.w;
        }
    }

    #pragma unroll
    for (int i = 0; i < 4; i++)
        #pragma unroll
        for (int j = 0; j < 4; j++)
            g_gv[(((b<<7) + (lane<<2) + j)<<10) + n0 + (w<<2) + i] = a2[i][j];

    __syncthreads();
    #pragma unroll
    for (int j = 0; j < 4; j++)
        s[w*132 + (lane<<2) + j] = a2[0][j] + a2[1][j] + a2[2][j] + a2[3][j];
    __syncthreads();
    if (tid < 128) {
        float ps = 0.f;
        #pragma unroll
        for (int ww = 0; ww < 8; ww++) ps += s[ww*132 + tid];
        g_part[(((b<<5) + nb)<<7) + tid] = ps;
    }
}

// ---------------- K3: channel attention ----------------
__global__ void __launch_bounds__(128) k_ca(const float* __restrict__ w1d,
                                            float* __restrict__ ca_out) {
    __shared__ float cam[130];
    int b = blockIdx.x, c = threadIdx.x;
    float sum = 0.f;
    for (int nb = 0; nb < 32; nb++) sum += g_part[(((b<<5) + nb)<<7) + c];
    cam[c+1] = sum * (1.0f/1024.0f);
    if (c == 0) { cam[0] = 0.f; cam[129] = 0.f; }
    __syncthreads();
    float y = w1d[0]*cam[c] + w1d[1]*cam[c+1] + w1d[2]*cam[c+2];
    float sg = 1.0f / (1.0f + __expf(-y));
    g_ca[(b<<7) + c] = sg;
    ca_out[(b<<7) + c] = sg;
}

// ---------------- K4: conv3x3(gv * ca) — 128 threads, 16 out-ch/CTA ----------------
// Same warp tile as R2 (4 out-ch x 8 rows x 8 cols per warp => 96 FMA per iv window),
// but 4 warps/CTA => smem 31.6KB, ~7 resident CTAs/SM, grid 512.
__global__ void __launch_bounds__(128) k_conv(const float* __restrict__ Wc,
                                              float* __restrict__ out) {
    __shared__ float in_s[16*350];   // [c16][ry(10) pitch35][cx(34)]
    __shared__ float w_s [16*144];   // [o16][c16*9]
    int b = blockIdx.x, ot = blockIdx.y, rt = blockIdx.z;
    int tid = threadIdx.x;
    int w = tid >> 5, lane = tid & 31;
    int row  = lane >> 2;            // 0..7
    int colb = (lane & 3) << 3;      // 0,8,16,24
    int r0 = rt << 3;

    float acc[4][8];
    #pragma unroll
    for (int i = 0; i < 4; i++)
        #pragma unroll
        for (int j = 0; j < 8; j++) acc[i][j] = 0.f;

    for (int cc = 0; cc < 8; cc++) {
        int cbase = cc << 4;
        __syncthreads();
        for (int idx = tid; idx < 5440; idx += 128) {
            int c   = idx / 340;
            int rem = idx - c*340;
            int ry  = rem / 34;
            int cx  = rem - ry*34;
            int gr = r0 - 1 + ry;
            int gc = cx - 1;
            float val = 0.f;
            if ((unsigned)gr < 32u && (unsigned)gc < 32u)
                val = g_gv[(((b<<7) + cbase + c)<<10) + (gr<<5) + gc]
                    * g_ca[(b<<7) + cbase + c];
            in_s[c*350 + ry*35 + cx] = val;
        }
        for (int idx = tid; idx < 2304; idx += 128) {
            int o   = idx / 144;
            int rem = idx - o*144;
            w_s[idx] = Wc[(((ot<<4) + o)*128 + cbase)*9 + rem];
        }
        __syncthreads();

        for (int c = 0; c < 16; c++) {
            #pragma unroll
            for (int ky = 0; ky < 3; ky++) {
                const float* ir = &in_s[c*350 + (row + ky)*35 + colb];
                float iv[10];
                #pragma unroll
                for (int t = 0; t < 10; t++) iv[t] = ir[t];
                #pragma unroll
                for (int o = 0; o < 4; o++) {
                    const float* wr = &w_s[((w<<2)+o)*144 + c*9 + ky*3];
                    float w0 = wr[0], w1 = wr[1], w2 = wr[2];
                    #pragma unroll
                    for (int xx = 0; xx < 8; xx++)
                        acc[o][xx] += w0*iv[xx] + w1*iv[xx+1] + w2*iv[xx+2];
                }
            }
        }
    }

    #pragma unroll
    for (int o = 0; o < 4; o++) {
        float* dst = out + (((size_t)((b<<8) + (ot<<4) + (w<<2) + o)*32 + r0 + row)<<5) + colb;
        *(float4*)&dst[0] = *(float4*)&acc[o][0];
        *(float4*)&dst[4] = *(float4*)&acc[o][4];
    }
}

extern "C" void kernel_launch(void* const* d_in, const int* in_sizes, int n_in,
                              void* d_out, int out_size) {
    const float* x   = (const float*)d_in[0];
    const float* Wq  = (const float*)d_in[1];
    const float* Wk  = (const float*)d_in[2];
    const float* Wv  = (const float*)d_in[3];
    const float* w1d = (const float*)d_in[4];
    const float* Wc  = (const float*)d_in[5];
    float* out_p  = (float*)d_out;
    float* gate_p = out_p + (size_t)BATCH*256*32*32;
    float* ca_p   = gate_p + (size_t)BATCH*NPIX*NPIX;

    cudaFuncSetAttribute(k_attn, cudaFuncAttributeMaxDynamicSharedMemorySize, SMEM2_BYTES);

    k_qkv <<<dim3(8,32), 256>>>(x, Wq, Wk, Wv);
    k_attn<<<dim3(8,32), 256, SMEM2_BYTES>>>(gate_p);
    k_ca  <<<8, 128>>>(w1d, ca_p);
    k_conv<<<dim3(8,16,4), 128>>>(Wc, out_p);
}

// round 9
// speedup vs baseline: 1.8986x; 1.0441x over previous
#include <cuda_runtime.h>

#define BATCH 8
#define NPIX  1024

__device__ float g_q  [BATCH*128*NPIX];
__device__ float g_k  [BATCH*128*NPIX];
__device__ float g_vT [BATCH*NPIX*128];
__device__ float g_gv [BATCH*128*NPIX];
__device__ float g_part[BATCH*32*128];
__device__ float g_ca [BATCH*128];
__device__ float g_cpart[2*BATCH*256*1024];   // split-K conv partials

// ---------------- K1: subsample + QKV projection ----------------
__global__ void __launch_bounds__(256) k_qkv(const float* __restrict__ x,
                                             const float* __restrict__ Wq,
                                             const float* __restrict__ Wk,
                                             const float* __restrict__ Wv) {
    __shared__ float xs[256*33];
    __shared__ float wt[16*132];
    int b = blockIdx.x, hs = blockIdx.y, tid = threadIdx.x;

    for (int idx = tid; idx < 256*32; idx += 256) {
        int c = idx >> 5, p = idx & 31;
        xs[c*33 + p] = x[(((b<<8) + c)*128 + (hs<<2))*128 + (p<<2)];
    }
    int to = tid >> 4, tp = tid & 15;
    int o0 = to*8, p0 = tp*2;
    int n  = (hs<<5) + p0;

    for (int mat = 0; mat < 3; mat++) {
        const float* W = (mat == 0) ? Wq : ((mat == 1) ? Wk : Wv);
        float acc[8][2];
        #pragma unroll
        for (int i = 0; i < 8; i++) { acc[i][0] = 0.f; acc[i][1] = 0.f; }

        for (int kc = 0; kc < 16; kc++) {
            __syncthreads();
            #pragma unroll
            for (int l = 0; l < 8; l++) {
                int idx = tid + l*256;
                int k = idx & 15, o = idx >> 4;
                wt[k*132 + o] = W[(o<<8) + (kc<<4) + k];
            }
            __syncthreads();
            #pragma unroll
            for (int k = 0; k < 16; k++) {
                float wv[8];
                *(float4*)&wv[0] = *(const float4*)&wt[k*132 + o0];
                *(float4*)&wv[4] = *(const float4*)&wt[k*132 + o0 + 4];
                float x0 = xs[((kc<<4)+k)*33 + p0];
                float x1 = xs[((kc<<4)+k)*33 + p0 + 1];
                #pragma unroll
                for (int i = 0; i < 8; i++) {
                    acc[i][0] += wv[i]*x0;
                    acc[i][1] += wv[i]*x1;
                }
            }
        }
        if (mat == 2) {
            #pragma unroll
            for (int j = 0; j < 2; j++)
                #pragma unroll
                for (int i = 0; i < 8; i++)
                    g_vT[(((b<<10) + n + j)<<7) + o0 + i] = acc[i][j];
        } else {
            float* dst = ((mat == 0) ? g_q : g_k) + (((b<<7) + o0)<<10) + n;
            #pragma unroll
            for (int i = 0; i < 8; i++) {
                dst[(i<<10) + 0] = acc[i][0];
                dst[(i<<10) + 1] = acc[i][1];
            }
        }
    }
}

// ---------------- K2: scores + softmax + gate + gv (fused, 32 rows/CTA) ----------------
#define S_PITCH  1028
#define KV_PITCH 132
#define Q_PITCH  36
#define SMEM2_BYTES ((32*S_PITCH + 128*KV_PITCH + 128*Q_PITCH)*4)

__global__ void __launch_bounds__(256) k_attn(float* __restrict__ gate_out) {
    extern __shared__ float sm[];
    float* s  = sm;
    float* kv = sm + 32*S_PITCH;
    float* qs = kv + 128*KV_PITCH;

    int b = blockIdx.x, nb = blockIdx.y;
    int n0 = nb << 5;
    int tid = threadIdx.x;
    int w = tid >> 5, lane = tid & 31;

    const float* qg  = g_q  + (size_t)b * (128*NPIX);
    const float* kg  = g_k  + (size_t)b * (128*NPIX);
    const float* vtg = g_vT + (size_t)b * (NPIX*128);

    for (int idx = tid; idx < 128*32; idx += 256) {
        int c = idx >> 5, ni = idx & 31;
        qs[c*Q_PITCH + ni] = qg[(c<<10) + n0 + ni];
    }

    for (int mt = 0; mt < 8; mt++) {
        int m0 = mt << 7;
        __syncthreads();
        for (int i = tid; i < 4096; i += 256) {
            int c = i >> 5, m4 = (i & 31) << 2;
            *(float4*)&kv[c*KV_PITCH + m4] = *(const float4*)&kg[(c<<10) + m0 + m4];
        }
        __syncthreads();
        float acc[4][4];
        #pragma unroll
        for (int i = 0; i < 4; i++)
            #pragma unroll
            for (int j = 0; j < 4; j++) acc[i][j] = 0.f;

        #pragma unroll 4
        for (int c = 0; c < 128; c++) {
            float4 qv = *(const float4*)&qs[c*Q_PITCH + (w<<2)];
            float4 kk = *(const float4*)&kv[c*KV_PITCH + (lane<<2)];
            acc[0][0] += qv.x*kk.x; acc[0][1] += qv.x*kk.y; acc[0][2] += qv.x*kk.z; acc[0][3] += qv.x*kk.w;
            acc[1][0] += qv.y*kk.x; acc[1][1] += qv.y*kk.y; acc[1][2] += qv.y*kk.z; acc[1][3] += qv.y*kk.w;
            acc[2][0] += qv.z*kk.x; acc[2][1] += qv.z*kk.y; acc[2][2] += qv.z*kk.z; acc[2][3] += qv.z*kk.w;
            acc[3][0] += qv.w*kk.x; acc[3][1] += qv.w*kk.y; acc[3][2] += qv.w*kk.z; acc[3][3] += qv.w*kk.w;
        }
        #pragma unroll
        for (int i = 0; i < 4; i++) {
            float4 v4; v4.x = acc[i][0]; v4.y = acc[i][1]; v4.z = acc[i][2]; v4.w = acc[i][3];
            *(float4*)&s[((w<<2) + i)*S_PITCH + m0 + (lane<<2)] = v4;
        }
    }
    __syncwarp();

    #pragma unroll
    for (int rr = 0; rr < 4; rr++) {
        int r = (w<<2) + rr;
        float* row = s + r*S_PITCH;
        float mx = -1e30f;
        for (int m = lane; m < 1024; m += 32) mx = fmaxf(mx, row[m]);
        #pragma unroll
        for (int off = 16; off; off >>= 1) mx = fmaxf(mx, __shfl_xor_sync(0xffffffffu, mx, off));
        float ssum = 0.f;
        for (int m = lane; m < 1024; m += 32) {
            float e = __expf(row[m] - mx);
            row[m] = e;
            ssum += e;
        }
        #pragma unroll
        for (int off = 16; off; off >>= 1) ssum += __shfl_xor_sync(0xffffffffu, ssum, off);
        float inv = 1.0f / ssum;
        float* go = gate_out + (((size_t)(b<<10) + n0 + r) << 10);
        for (int m = lane; m < 1024; m += 32) {
            float gte = row[m] * inv;
            row[m] = gte;
            go[m] = gte;
        }
    }

    float a2[4][4];
    #pragma unroll
    for (int i = 0; i < 4; i++)
        #pragma unroll
        for (int j = 0; j < 4; j++) a2[i][j] = 0.f;

    for (int mt = 0; mt < 8; mt++) {
        int m0 = mt << 7;
        __syncthreads();
        for (int i = tid; i < 4096; i += 256) {
            int m = i >> 5, c4 = (i & 31) << 2;
            *(float4*)&kv[m*KV_PITCH + c4] = *(const float4*)&vtg[((m0 + m) << 7) + c4];
        }
        __syncthreads();
        for (int m = 0; m < 128; m += 2) {
            float2 g0 = *(const float2*)&s[((w<<2)+0)*S_PITCH + m0 + m];
            float2 g1 = *(const float2*)&s[((w<<2)+1)*S_PITCH + m0 + m];
            float2 g2 = *(const float2*)&s[((w<<2)+2)*S_PITCH + m0 + m];
            float2 g3 = *(const float2*)&s[((w<<2)+3)*S_PITCH + m0 + m];
            float4 va = *(const float4*)&kv[m*KV_PITCH + (lane<<2)];
            float4 vb = *(const float4*)&kv[(m+1)*KV_PITCH + (lane<<2)];
            a2[0][0] += g0.x*va.x + g0.y*vb.x;  a2[0][1] += g0.x*va.y + g0.y*vb.y;
            a2[0][2] += g0.x*va.z + g0.y*vb.z;  a2[0][3] += g0.x*va.w + g0.y*vb.w;
            a2[1][0] += g1.x*va.x + g1.y*vb.x;  a2[1][1] += g1.x*va.y + g1.y*vb.y;
            a2[1][2] += g1.x*va.z + g1.y*vb.z;  a2[1][3] += g1.x*va.w + g1.y*vb.w;
            a2[2][0] += g2.x*va.x + g2.y*vb.x;  a2[2][1] += g2.x*va.y + g2.y*vb.y;
            a2[2][2] += g2.x*va.z + g2.y*vb.z;  a2[2][3] += g2.x*va.w + g2.y*vb.w;
            a2[3][0] += g3.x*va.x + g3.y*vb.x;  a2[3][1] += g3.x*va.y + g3.y*vb.y;
            a2[3][2] += g3.x*va.z + g3.y*vb.z;  a2[3][3] += g3.x*va.w + g3.y*vb.w;
        }
    }

    #pragma unroll
    for (int i = 0; i < 4; i++)
        #pragma unroll
        for (int j = 0; j < 4; j++)
            g_gv[(((b<<7) + (lane<<2) + j)<<10) + n0 + (w<<2) + i] = a2[i][j];

    __syncthreads();
    #pragma unroll
    for (int j = 0; j < 4; j++)
        s[w*132 + (lane<<2) + j] = a2[0][j] + a2[1][j] + a2[2][j] + a2[3][j];
    __syncthreads();
    if (tid < 128) {
        float ps = 0.f;
        #pragma unroll
        for (int ww = 0; ww < 8; ww++) ps += s[ww*132 + tid];
        g_part[(((b<<5) + nb)<<7) + tid] = ps;
    }
}

// ---------------- K3: channel attention ----------------
__global__ void __launch_bounds__(128) k_ca(const float* __restrict__ w1d,
                                            float* __restrict__ ca_out) {
    __shared__ float cam[130];
    int b = blockIdx.x, c = threadIdx.x;
    float sum = 0.f;
    for (int nb = 0; nb < 32; nb++) sum += g_part[(((b<<5) + nb)<<7) + c];
    cam[c+1] = sum * (1.0f/1024.0f);
    if (c == 0) { cam[0] = 0.f; cam[129] = 0.f; }
    __syncthreads();
    float y = w1d[0]*cam[c] + w1d[1]*cam[c+1] + w1d[2]*cam[c+2];
    float sg = 1.0f / (1.0f + __expf(-y));
    g_ca[(b<<7) + c] = sg;
    ca_out[(b<<7) + c] = sg;
}

// ---------------- K4: conv3x3(gv * ca), split-K over input channels ----------------
// grid (8, 16 octile, 8 = rt*2+half). Each CTA: 16 out-ch, 8 rows, 4 input-ch chunks.
// 1024 CTAs -> ~7 resident/SM (smem 31.6KB, 72 regs).
__global__ void __launch_bounds__(128) k_conv(const float* __restrict__ Wc) {
    __shared__ float in_s[16*350];
    __shared__ float w_s [16*144];
    int b = blockIdx.x, ot = blockIdx.y;
    int rt = blockIdx.z >> 1, kh = blockIdx.z & 1;
    int tid = threadIdx.x;
    int w = tid >> 5, lane = tid & 31;
    int row  = lane >> 2;
    int colb = (lane & 3) << 3;
    int r0 = rt << 3;

    float acc[4][8];
    #pragma unroll
    for (int i = 0; i < 4; i++)
        #pragma unroll
        for (int j = 0; j < 8; j++) acc[i][j] = 0.f;

    for (int cc = kh*4; cc < kh*4 + 4; cc++) {
        int cbase = cc << 4;
        __syncthreads();
        for (int idx = tid; idx < 5440; idx += 128) {
            int c   = idx / 340;
            int rem = idx - c*340;
            int ry  = rem / 34;
            int cx  = rem - ry*34;
            int gr = r0 - 1 + ry;
            int gc = cx - 1;
            float val = 0.f;
            if ((unsigned)gr < 32u && (unsigned)gc < 32u)
                val = g_gv[(((b<<7) + cbase + c)<<10) + (gr<<5) + gc]
                    * g_ca[(b<<7) + cbase + c];
            in_s[c*350 + ry*35 + cx] = val;
        }
        for (int idx = tid; idx < 2304; idx += 128) {
            int o   = idx / 144;
            int rem = idx - o*144;
            w_s[idx] = Wc[(((ot<<4) + o)*128 + cbase)*9 + rem];
        }
        __syncthreads();

        for (int c = 0; c < 16; c++) {
            #pragma unroll
            for (int ky = 0; ky < 3; ky++) {
                const float* ir = &in_s[c*350 + (row + ky)*35 + colb];
                float iv[10];
                #pragma unroll
                for (int t = 0; t < 10; t++) iv[t] = ir[t];
                #pragma unroll
                for (int o = 0; o < 4; o++) {
                    const float* wr = &w_s[((w<<2)+o)*144 + c*9 + ky*3];
                    float w0 = wr[0], w1 = wr[1], w2 = wr[2];
                    #pragma unroll
                    for (int xx = 0; xx < 8; xx++)
                        acc[o][xx] += w0*iv[xx] + w1*iv[xx+1] + w2*iv[xx+2];
                }
            }
        }
    }

    float* part = g_cpart + (size_t)kh * (BATCH*256*1024);
    #pragma unroll
    for (int o = 0; o < 4; o++) {
        float* dst = part + (((size_t)((b<<8) + (ot<<4) + (w<<2) + o)*32 + r0 + row)<<5) + colb;
        *(float4*)&dst[0] = *(float4*)&acc[o][0];
        *(float4*)&dst[4] = *(float4*)&acc[o][4];
    }
}

// ---------------- K5: combine split-K partials ----------------
__global__ void __launch_bounds__(256) k_add(float* __restrict__ out) {
    int i = (blockIdx.x*256 + threadIdx.x) << 2;
    const float* p0 = g_cpart;
    const float* p1 = g_cpart + (size_t)BATCH*256*1024;
    float4 a = *(const float4*)&p0[i];
    float4 c = *(const float4*)&p1[i];
    a.x += c.x; a.y += c.y; a.z += c.z; a.w += c.w;
    *(float4*)&out[i] = a;
}

extern "C" void kernel_launch(void* const* d_in, const int* in_sizes, int n_in,
                              void* d_out, int out_size) {
    const float* x   = (const float*)d_in[0];
    const float* Wq  = (const float*)d_in[1];
    const float* Wk  = (const float*)d_in[2];
    const float* Wv  = (const float*)d_in[3];
    const float* w1d = (const float*)d_in[4];
    const float* Wc  = (const float*)d_in[5];
    float* out_p  = (float*)d_out;
    float* gate_p = out_p + (size_t)BATCH*256*32*32;
    float* ca_p   = gate_p + (size_t)BATCH*NPIX*NPIX;

    cudaFuncSetAttribute(k_attn, cudaFuncAttributeMaxDynamicSharedMemorySize, SMEM2_BYTES);

    k_qkv <<<dim3(8,32), 256>>>(x, Wq, Wk, Wv);
    k_attn<<<dim3(8,32), 256, SMEM2_BYTES>>>(gate_p);
    k_ca  <<<8, 128>>>(w1d, ca_p);
    k_conv<<<dim3(8,16,8), 128>>>(Wc);
    k_add <<<(BATCH*256*1024)/1024, 256>>>(out_p);
}